// round 1
// baseline (speedup 1.0000x reference)
#include <cuda_runtime.h>

#define EPS 1e-4f

constexpr int IN_DIM = 30;
constexpr int D1 = 20;
constexpr int D2 = 15;
constexpr int N1 = 20;      // first eigensolve size
constexpr int N2 = 16;      // second eigensolve size (15 padded to 16)
constexpr int PITCH = 21;   // coprime with 32 -> conflict-free column access
constexpr int WPB = 4;      // warps (matrices) per block
constexpr int SWEEPS1 = 8;
constexpr int SWEEPS2 = 8;

struct __align__(16) MatWS {
    float X[960];            // 30x30 input (dense), later reused as B (20 x PITCH)
    float A[N1 * PITCH];     // working symmetric matrix (20x21; stage2 uses 16x21)
    float V[N1 * PITCH];     // eigenvectors / scratch
    int   pp[10], qq[10];    // rotation pair indices per round
    float cc[10], ss[10];    // rotation cos/sin per round
    float lw[16];            // log-eigenvalues
};

struct __align__(16) SmemT {
    float W1[D1 * IN_DIM];   // 20x30
    float W2[D2 * D1];       // 15x20
    MatWS m[WPB];
};

// Warp-parallel cyclic Jacobi with round-robin (tournament) parallel ordering.
// A <- J^T A J applied as (A*J) then (J^T * ...); V <- V*J.
template <int N>
__device__ __forceinline__ void jacobi_warp(MatWS& ws, int sweeps, int lane) {
    constexpr int NP = N / 2;
    for (int sw = 0; sw < sweeps; ++sw) {
        for (int r = 0; r < N - 1; ++r) {
            if (lane < NP) {
                int p, q;
                if (lane == 0) { p = N - 1; q = r; }
                else {
                    p = r + lane;      if (p >= N - 1) p -= (N - 1);
                    q = r - lane;      if (q < 0)      q += (N - 1);
                }
                float app = ws.A[p * PITCH + p];
                float aqq = ws.A[q * PITCH + q];
                float apq = ws.A[p * PITCH + q];
                float c = 1.0f, s = 0.0f;
                if (fabsf(apq) > 1e-30f) {
                    float tau = (aqq - app) / (2.0f * apq);
                    float t = copysignf(1.0f, tau) /
                              (fabsf(tau) + sqrtf(fmaf(tau, tau, 1.0f)));
                    c = rsqrtf(fmaf(t, t, 1.0f));
                    s = t * c;
                }
                ws.pp[lane] = p; ws.qq[lane] = q;
                ws.cc[lane] = c; ws.ss[lane] = s;
            }
            __syncwarp();
            // Phase 1: column rotations  A <- A*J  (pairs have disjoint columns)
            for (int idx = lane; idx < NP * N; idx += 32) {
                int k = idx / N, i = idx - k * N;
                int p = ws.pp[k], q = ws.qq[k];
                float c = ws.cc[k], s = ws.ss[k];
                float aip = ws.A[i * PITCH + p];
                float aiq = ws.A[i * PITCH + q];
                ws.A[i * PITCH + p] = fmaf(c, aip, -s * aiq);
                ws.A[i * PITCH + q] = fmaf(s, aip,  c * aiq);
            }
            __syncwarp();
            // Phase 2: row rotations A <- J^T*A   and   V <- V*J
            for (int idx = lane; idx < 2 * NP * N; idx += 32) {
                bool rowA = idx < NP * N;
                int id2 = rowA ? idx : idx - NP * N;
                int k = id2 / N, j = id2 - k * N;
                int p = ws.pp[k], q = ws.qq[k];
                float c = ws.cc[k], s = ws.ss[k];
                if (rowA) {
                    float apj = ws.A[p * PITCH + j];
                    float aqj = ws.A[q * PITCH + j];
                    ws.A[p * PITCH + j] = fmaf(c, apj, -s * aqj);
                    ws.A[q * PITCH + j] = fmaf(s, apj,  c * aqj);
                } else {
                    float vjp = ws.V[j * PITCH + p];
                    float vjq = ws.V[j * PITCH + q];
                    ws.V[j * PITCH + p] = fmaf(c, vjp, -s * vjq);
                    ws.V[j * PITCH + q] = fmaf(s, vjp,  c * vjq);
                }
            }
            __syncwarp();
        }
    }
}

__global__ __launch_bounds__(WPB * 32)
void spdnet_kernel(const float* __restrict__ Xg,
                   const float* __restrict__ W1g,
                   const float* __restrict__ W2g,
                   float* __restrict__ out, int nb) {
    __shared__ SmemT sm;
    int tid  = threadIdx.x;
    int warp = tid >> 5;
    int lane = tid & 31;

    for (int i = tid; i < D1 * IN_DIM; i += WPB * 32) sm.W1[i] = W1g[i];
    for (int i = tid; i < D2 * D1;    i += WPB * 32) sm.W2[i] = W2g[i];
    __syncthreads();

    int m = blockIdx.x * WPB + warp;
    if (m >= nb) return;   // warp-uniform exit; only __syncwarp below

    MatWS& ws = sm.m[warp];

    // ---- Load X (900 floats, 16B-aligned per matrix) ----
    {
        const float4* xg = reinterpret_cast<const float4*>(Xg + (size_t)m * 900);
        float4* xs = reinterpret_cast<float4*>(ws.X);
        for (int i = lane; i < 225; i += 32) xs[i] = xg[i];
    }
    __syncwarp();

    // ---- bimap1: raw M = W1 * X * W1^T  (20x20), rows across lanes ----
    if (lane < D1) {
        int o = lane;
        float t[IN_DIM];
        #pragma unroll
        for (int j = 0; j < IN_DIM; ++j) t[j] = 0.0f;
        for (int i = 0; i < IN_DIM; ++i) {
            float w = sm.W1[o * IN_DIM + i];
            #pragma unroll
            for (int j = 0; j < IN_DIM; ++j)
                t[j] = fmaf(w, ws.X[i * IN_DIM + j], t[j]);
        }
        for (int p = 0; p < D1; ++p) {
            float acc = 0.0f;
            #pragma unroll
            for (int j = 0; j < IN_DIM; ++j)
                acc = fmaf(t[j], sm.W1[p * IN_DIM + j], acc);
            ws.V[o * PITCH + p] = acc;   // V buffer as raw scratch
        }
    }
    __syncwarp();
    // symmetrize + eps*I -> A
    for (int idx = lane; idx < D1 * D1; idx += 32) {
        int i = idx / D1, j = idx - i * D1;
        float v = 0.5f * (ws.V[i * PITCH + j] + ws.V[j * PITCH + i]);
        ws.A[i * PITCH + j] = v + (i == j ? EPS : 0.0f);
    }
    __syncwarp();
    for (int idx = lane; idx < D1 * D1; idx += 32) {
        int i = idx / D1, j = idx - i * D1;
        ws.V[i * PITCH + j] = (i == j) ? 1.0f : 0.0f;
    }
    __syncwarp();

    // ---- eigensolve 20x20 ----
    jacobi_warp<N1>(ws, SWEEPS1, lane);

    // ---- ReEig recompose: B = V * max(w,EPS) * V^T  -> into X buffer (pitch 21)
    if (lane < D1) {
        int o = lane;
        float b[D1];
        #pragma unroll
        for (int j = 0; j < D1; ++j) b[j] = 0.0f;
        for (int k = 0; k < D1; ++k) {
            float wk  = fmaxf(ws.A[k * PITCH + k], EPS);
            float vok = ws.V[o * PITCH + k] * wk;
            #pragma unroll
            for (int j = 0; j < D1; ++j)
                b[j] = fmaf(vok, ws.V[j * PITCH + k], b[j]);
        }
        #pragma unroll
        for (int j = 0; j < D1; ++j) ws.X[o * PITCH + j] = b[j];
    }
    __syncwarp();

    // ---- bimap2: raw C = W2 * B * W2^T (15x15) into V scratch ----
    if (lane < D2) {
        int o = lane;
        float t2[D1];
        #pragma unroll
        for (int j = 0; j < D1; ++j) t2[j] = 0.0f;
        for (int i = 0; i < D1; ++i) {
            float w = sm.W2[o * D1 + i];
            #pragma unroll
            for (int j = 0; j < D1; ++j)
                t2[j] = fmaf(w, ws.X[i * PITCH + j], t2[j]);
        }
        for (int p = 0; p < D2; ++p) {
            float acc = 0.0f;
            #pragma unroll
            for (int j = 0; j < D1; ++j)
                acc = fmaf(t2[j], sm.W2[p * D1 + j], acc);
            ws.V[o * PITCH + p] = acc;
        }
    }
    __syncwarp();
    // symmetrize + eps*I into padded 16x16 A (row/col 15 zero)
    for (int idx = lane; idx < N2 * N2; idx += 32) {
        int i = idx >> 4, j = idx & 15;
        float v = 0.0f;
        if (i < D2 && j < D2) {
            v = 0.5f * (ws.V[i * PITCH + j] + ws.V[j * PITCH + i]);
            if (i == j) v += EPS;
        }
        ws.A[i * PITCH + j] = v;
    }
    __syncwarp();
    for (int idx = lane; idx < N2 * N2; idx += 32) {
        int i = idx >> 4, j = idx & 15;
        ws.V[i * PITCH + j] = (i == j) ? 1.0f : 0.0f;
    }
    __syncwarp();

    // ---- eigensolve (15x15 padded to 16); second reeig folds into logeig ----
    jacobi_warp<N2>(ws, SWEEPS2, lane);

    if (lane < D2)
        ws.lw[lane] = logf(fmaxf(ws.A[lane * PITCH + lane], EPS));
    __syncwarp();

    // ---- output: upper triangle of V * log(max(w,EPS)) * V^T ----
    for (int t = lane; t < 120; t += 32) {
        int tt = t, i = 0;
        while (tt >= D2 - i) { tt -= D2 - i; ++i; }
        int j = i + tt;
        float acc = 0.0f;
        #pragma unroll
        for (int k = 0; k < D2; ++k)
            acc = fmaf(ws.V[i * PITCH + k] * ws.lw[k], ws.V[j * PITCH + k], acc);
        out[(size_t)m * 120 + t] = acc;
    }
}

extern "C" void kernel_launch(void* const* d_in, const int* in_sizes, int n_in,
                              void* d_out, int out_size) {
    const float* X  = (const float*)d_in[0];
    const float* W1 = (const float*)d_in[1];
    const float* W2 = (const float*)d_in[2];
    float* out = (float*)d_out;
    int nb = in_sizes[0] / (IN_DIM * IN_DIM);
    int blocks = (nb + WPB - 1) / WPB;
    spdnet_kernel<<<blocks, WPB * 32>>>(X, W1, W2, out, nb);
}

// round 2
// speedup vs baseline: 2.7815x; 2.7815x over previous
#include <cuda_runtime.h>

#define EPS 1e-4f
constexpr int IN_DIM = 30;
constexpr int D1 = 20;
constexpr int D2 = 15;
constexpr int WPB = 4;          // warps (matrices) per block
constexpr int SW1 = 6, SW2 = 6; // Jacobi sweeps per stage
constexpr unsigned FULL = 0xffffffffu;

// Tournament migration: NEW[l] = OLD[sigma(l)]. Position 0 fixed.
__host__ __device__ constexpr int sigma(int N, int l) {
    if (l >= N) return l;
    if (l == 0) return 0;
    if (l == N - 1) return N - 2;
    if (l & 1) return l + 2;   // odd slots move down the ring
    if (l == 2) return 1;
    return l - 2;              // even slots >= 4
}

// Register/shuffle parallel Jacobi. Lane = column position of A; pairs are
// fixed lanes (2k,2k+1); vt = row `lane` of V (columns = positions).
template <int N>
__device__ __forceinline__ void jacobi_reg(float* a, float* vt, float& dg,
                                           int lane, int sig, int sweeps) {
    const int role = lane & 1;           // 0 = p-role (even pos), 1 = q-role
    for (int sw = 0; sw < sweeps; ++sw) {
        for (int r = 0; r < N - 1; ++r) {
            // --- gather rotation inputs ---
            float d_oth = __shfl_xor_sync(FULL, dg, 1);
            float off = 0.0f;
            #pragma unroll
            for (int k = 0; k < N / 2; ++k)
                if ((lane >> 1) == k) off = role ? a[2 * k] : a[2 * k + 1];
            float apq = __shfl_sync(FULL, off, lane & ~1);  // canonical (even lane's copy)
            float d_e = role ? d_oth : dg;
            float d_o = role ? dg : d_oth;
            // --- rotation (Golub): zero A[p][q], p = even position ---
            float c = 1.0f, s = 0.0f, t = 0.0f;
            if (fabsf(apq) > 1e-30f) {
                float tau = (d_o - d_e) / (2.0f * apq);
                t = copysignf(1.0f, tau) / (fabsf(tau) + sqrtf(fmaf(tau, tau, 1.0f)));
                c = rsqrtf(fmaf(t, t, 1.0f));
                s = t * c;
            }
            c = __shfl_sync(FULL, c, lane & ~1);   // bit-identical across the pair
            s = __shfl_sync(FULL, s, lane & ~1);
            // --- column phase: A <- A*J (partner exchange via shfl_xor) ---
            float sg = role ? s : -s;
            #pragma unroll
            for (int i = 0; i < N; ++i) {
                float o = __shfl_xor_sync(FULL, a[i], 1);
                a[i] = fmaf(c, a[i], sg * o);
            }
            // --- analytic diag update: app' = app - t*apq ; aqq' = aqq + t*apq ---
            dg = role ? fmaf(t, apq, dg) : fmaf(-t, apq, dg);
            // --- row phase: A <- J^T*(A*J); V <- V*J (register-local, static idx) ---
            #pragma unroll
            for (int k = 0; k < N / 2; ++k) {
                float ck = __shfl_sync(FULL, c, 2 * k);
                float sk = __shfl_sync(FULL, s, 2 * k);
                float ae = a[2 * k], ao = a[2 * k + 1];
                a[2 * k]     = fmaf(ck, ae, -sk * ao);
                a[2 * k + 1] = fmaf(sk, ae,  ck * ao);
                float ve = vt[2 * k], vo = vt[2 * k + 1];
                vt[2 * k]     = fmaf(ck, ve, -sk * vo);
                vt[2 * k + 1] = fmaf(sk, ve,  ck * vo);
            }
            // --- tournament migration: rows (reg perm) + cols (lane shfl) ---
            float tmp[N];
            #pragma unroll
            for (int i = 0; i < N; ++i) tmp[i] = a[sigma(N, i)];
            #pragma unroll
            for (int i = 0; i < N; ++i) a[i] = __shfl_sync(FULL, tmp[i], sig);
            #pragma unroll
            for (int i = 0; i < N; ++i) tmp[i] = vt[sigma(N, i)];
            #pragma unroll
            for (int i = 0; i < N; ++i) vt[i] = tmp[i];
            dg = __shfl_sync(FULL, dg, sig);
        }
    }
}

__global__ __launch_bounds__(WPB * 32)
void spdnet_kernel(const float* __restrict__ Xg,
                   const float* __restrict__ W1g,
                   const float* __restrict__ W2g,
                   float* __restrict__ out, int nb) {
    __shared__ float W1s[D1 * IN_DIM];           // 20x30
    __shared__ float W2s[D2 * D1];               // 15x20
    __shared__ __align__(16) float scr_all[WPB][960];

    int tid = threadIdx.x, warp = tid >> 5, lane = tid & 31;
    for (int i = tid; i < D1 * IN_DIM; i += WPB * 32) W1s[i] = W1g[i];
    for (int i = tid; i < D2 * D1;    i += WPB * 32) W2s[i] = W2g[i];
    __syncthreads();

    int m = blockIdx.x * WPB + warp;
    if (m >= nb) return;           // warp-uniform; only warp-level sync below
    float* scr = scr_all[warp];

    // ================= Load X (pitch 32) and symmetrize =================
    {
        const float* xg = Xg + (size_t)m * 900;
        for (int e = lane; e < 900; e += 32) {
            int i = e / 30, k = e - i * 30;
            scr[i * 32 + k] = xg[e];
        }
        for (int e = lane; e < 60; e += 32)            // zero pad cols 30,31
            scr[(e >> 1) * 32 + 30 + (e & 1)] = 0.0f;
    }
    __syncwarp();
    for (int e = lane; e < 900; e += 32) {
        int i = e / 30, k = e - i * 30;
        if (i < k) {
            float v = 0.5f * (scr[i * 32 + k] + scr[k * 32 + i]);
            scr[i * 32 + k] = v; scr[k * 32 + i] = v;
        }
    }
    __syncwarp();

    // ================= bimap1: A = W1 * Xs * W1^T + EPS*I ===============
    float a[D1], vt[D1], dg = 1.0f;
    #pragma unroll
    for (int i = 0; i < D1; ++i) { a[i] = 0.0f; vt[i] = 0.0f; }
    if (lane < D1) {
        float wreg[32];
        #pragma unroll
        for (int k = 0; k < IN_DIM; ++k) wreg[k] = W1s[lane * IN_DIM + k];
        wreg[30] = 0.0f; wreg[31] = 0.0f;
        float t[IN_DIM];
        for (int i = 0; i < IN_DIM; ++i) {        // t = Xs * w1_lane
            const float4* x4 = reinterpret_cast<const float4*>(&scr[i * 32]);
            float acc = 0.0f;
            #pragma unroll
            for (int q = 0; q < 8; ++q) {
                float4 x = x4[q];
                acc = fmaf(x.x, wreg[4 * q + 0], acc);
                acc = fmaf(x.y, wreg[4 * q + 1], acc);
                acc = fmaf(x.z, wreg[4 * q + 2], acc);
                acc = fmaf(x.w, wreg[4 * q + 3], acc);
            }
            t[i] = acc;
        }
        #pragma unroll
        for (int r = 0; r < D1; ++r) {            // a = W1 * t  (column `lane` of A)
            float acc = 0.0f;
            #pragma unroll
            for (int i = 0; i < IN_DIM; ++i)
                acc = fmaf(W1s[r * IN_DIM + i], t[i], acc);
            a[r] = acc;
            if (r == lane) { a[r] += EPS; dg = a[r]; }
        }
        #pragma unroll
        for (int k = 0; k < D1; ++k) vt[k] = (k == lane) ? 1.0f : 0.0f;
    }

    // ================= eigensolve 20x20 =================================
    jacobi_reg<D1>(a, vt, dg, lane, sigma(D1, lane), SW1);

    // ====== fused reeig + bimap2: C = Z Z^T,  Z = W2 * (V * sqrt(g)) ====
    float g = sqrtf(fmaxf(dg, EPS));
    #pragma unroll
    for (int k = 0; k < D1; ++k) {
        float rk = __shfl_sync(FULL, g, k);
        vt[k] *= rk;
    }
    if (lane < D1) {
        #pragma unroll
        for (int k = 0; k < D1; ++k) scr[lane * 24 + k] = vt[k]; // Vs (pitch 24)
    }
    __syncwarp();
    float z[D1];
    #pragma unroll
    for (int k = 0; k < D1; ++k) z[k] = 0.0f;
    if (lane < D2) {
        float w2r[D1];
        #pragma unroll
        for (int r = 0; r < D1; ++r) w2r[r] = W2s[lane * D1 + r];
        for (int r = 0; r < D1; ++r) {
            const float4* v4 = reinterpret_cast<const float4*>(&scr[r * 24]);
            float w = w2r[r];
            #pragma unroll
            for (int q = 0; q < 5; ++q) {
                float4 x = v4[q];
                z[4 * q + 0] = fmaf(w, x.x, z[4 * q + 0]);
                z[4 * q + 1] = fmaf(w, x.y, z[4 * q + 1]);
                z[4 * q + 2] = fmaf(w, x.z, z[4 * q + 2]);
                z[4 * q + 3] = fmaf(w, x.w, z[4 * q + 3]);
            }
        }
    }
    __syncwarp();
    if (lane < D2) {
        #pragma unroll
        for (int k = 0; k < D1; ++k) scr[480 + lane * 24 + k] = z[k]; // Zs
    }
    __syncwarp();

    float a2[16], vt2[16], dg2 = 1.0f;
    #pragma unroll
    for (int i = 0; i < 16; ++i) { a2[i] = 0.0f; vt2[i] = 0.0f; }
    if (lane < 16) {
        #pragma unroll
        for (int b = 0; b < D2; ++b) {            // A2[b][lane] = Zrow_b . z
            const float4* zb = reinterpret_cast<const float4*>(&scr[480 + b * 24]);
            float acc = 0.0f;
            #pragma unroll
            for (int q = 0; q < 5; ++q) {
                float4 x = zb[q];
                acc = fmaf(x.x, z[4 * q + 0], acc);
                acc = fmaf(x.y, z[4 * q + 1], acc);
                acc = fmaf(x.z, z[4 * q + 2], acc);
                acc = fmaf(x.w, z[4 * q + 3], acc);
            }
            a2[b] = acc;
        }
        a2[15] = 0.0f;                            // padded dim decoupled
        #pragma unroll
        for (int b = 0; b < 16; ++b)
            if (b == lane) { a2[b] += EPS; dg2 = a2[b]; }
        #pragma unroll
        for (int k = 0; k < 16; ++k) vt2[k] = (k == lane) ? 1.0f : 0.0f;
    }

    // ================= eigensolve 16x16 (15 + 1 padded) =================
    jacobi_reg<16>(a2, vt2, dg2, lane, sigma(16, lane), SW2);

    // ============== logeig recompose, upper-triangle output =============
    float lw = logf(fmaxf(dg2, EPS));
    #pragma unroll
    for (int k = 0; k < 16; ++k) {
        float lwk = __shfl_sync(FULL, lw, k);
        float raw = vt2[k];
        if (lane < D2) {
            scr[lane * 16 + k]       = raw;        // raw rows of V2
            scr[256 + lane * 16 + k] = raw * lwk;  // scaled rows
        }
    }
    __syncwarp();
    for (int tt = lane; tt < 120; tt += 32) {
        int i = 0, rem = tt;
        while (rem >= D2 - i) { rem -= D2 - i; ++i; }
        int j = i + rem;
        const float4* ri = reinterpret_cast<const float4*>(&scr[256 + i * 16]);
        const float4* rj = reinterpret_cast<const float4*>(&scr[j * 16]);
        float acc = 0.0f;
        #pragma unroll
        for (int q = 0; q < 4; ++q) {
            float4 x = ri[q], y = rj[q];
            acc = fmaf(x.x, y.x, fmaf(x.y, y.y, fmaf(x.z, y.z, fmaf(x.w, y.w, acc))));
        }
        out[(size_t)m * 120 + tt] = acc;
    }
}

extern "C" void kernel_launch(void* const* d_in, const int* in_sizes, int n_in,
                              void* d_out, int out_size) {
    const float* X  = (const float*)d_in[0];
    const float* W1 = (const float*)d_in[1];
    const float* W2 = (const float*)d_in[2];
    float* out = (float*)d_out;
    int nb = in_sizes[0] / (IN_DIM * IN_DIM);
    int blocks = (nb + WPB - 1) / WPB;
    spdnet_kernel<<<blocks, WPB * 32>>>(X, W1, W2, out, nb);
}